// round 6
// baseline (speedup 1.0000x reference)
#include <cuda_runtime.h>

#define KK    1056
#define NN    2112
#define MM    1056
#define DVx   5
#define EE    6336   // MM * (DVx+1)
#define NSYMs 528
#define BB    1024
#define NITERs 20

// ---- static device scratch (no allocations allowed) ----
__device__ float g_llr[NN * BB];          // intrinsic channel LLRs, [n][b]
__device__ float g_L[NN * BB];            // llr + sum of c2v (posterior), [n][b]
__device__ float g_c2v[EE * BB];          // check->variable messages, [e][b]
__device__ unsigned char g_bitsT[KK * BB];// transposed info bits, [k][b]
__device__ int g_cnt[NN];
__device__ int g_off[NN + 1];             // CSR offsets per variable node
__device__ int g_var_edges[EE];           // CSR edge lists (deterministic order)

// ---------------- setup kernels ----------------

__global__ void k_transpose(const int* __restrict__ bits) {
    int t = blockIdx.x * blockDim.x + threadIdx.x;
    if (t < BB * KK) {
        int b = t / KK, k = t - b * KK;
        g_bitsT[k * BB + b] = (unsigned char)bits[t];
    }
}

__global__ void k_zero_cnt() {
    int t = blockIdx.x * blockDim.x + threadIdx.x;
    if (t < NN) g_cnt[t] = 0;
}

__global__ void k_count(const int* __restrict__ vn) {
    int e = blockIdx.x * blockDim.x + threadIdx.x;
    if (e < EE) atomicAdd(&g_cnt[vn[e]], 1);
}

// single-block exclusive scan over NN=2112 counts (3 per thread, 1024 threads)
__global__ void k_scan() {
    __shared__ int sh[1024];
    int tid = threadIdx.x;
    int i0 = tid * 3;
    int c0 = (i0 + 0 < NN) ? g_cnt[i0 + 0] : 0;
    int c1 = (i0 + 1 < NN) ? g_cnt[i0 + 1] : 0;
    int c2 = (i0 + 2 < NN) ? g_cnt[i0 + 2] : 0;
    int sum = c0 + c1 + c2;
    sh[tid] = sum;
    __syncthreads();
    for (int off = 1; off < 1024; off <<= 1) {
        int v = (tid >= off) ? sh[tid - off] : 0;
        __syncthreads();
        sh[tid] += v;
        __syncthreads();
    }
    int base = sh[tid] - sum;  // exclusive prefix for this thread's chunk
    if (i0 + 0 < NN) g_off[i0 + 0] = base;
    if (i0 + 1 < NN) g_off[i0 + 1] = base + c0;
    if (i0 + 2 < NN) g_off[i0 + 2] = base + c0 + c1;
    if (tid == 1023) g_off[NN] = sh[1023];
}

// deterministic CSR fill: rank of edge e among edges with same variable =
// count of earlier edges hitting the same vn. O(E^2) total but E=6336 -> cheap.
__global__ void k_fill(const int* __restrict__ vn) {
    int e = blockIdx.x * blockDim.x + threadIdx.x;
    if (e < EE) {
        int v = __ldg(vn + e);
        int r = 0;
        for (int q = 0; q < e; q++) r += (__ldg(vn + q) == v);
        g_var_edges[g_off[v] + r] = e;
    }
}

__global__ void k_zero_c2v() {
    int t = blockIdx.x * blockDim.x + threadIdx.x;
    if (t < EE * BB / 4)
        reinterpret_cast<float4*>(g_c2v)[t] = make_float4(0.f, 0.f, 0.f, 0.f);
}

// ---------------- encode + QAM map + AWGN + APP demap ----------------
// one thread per (symbol s, batch b); writes llr for the 4 bits of that symbol.
__global__ void k_demap(const int* __restrict__ a_idx,
                        const float* __restrict__ pre,
                        const float* __restrict__ pim,
                        const float* __restrict__ nre,
                        const float* __restrict__ nim,
                        const float* __restrict__ ebno) {
    int b = blockIdx.x * blockDim.x + threadIdx.x;
    int s = blockIdx.y;

    float eb = __ldg(ebno);
    float p10 = exp10f(eb / 10.0f);
    float no = 1.0f / (p10 * 0.5f * 4.0f);   // coderate = K/N = 0.5, NBPS=4
    float sigma = sqrtf(no * 0.5f);
    float inv = -1.0f / no;

    float cr[16], ci[16];
#pragma unroll
    for (int i = 0; i < 16; i++) { cr[i] = __ldg(pre + i); ci[i] = __ldg(pim + i); }

    int nbase = 4 * s;
    int c[4];
    if (nbase < KK) {            // info-bit region (uniform branch: s < 264)
#pragma unroll
        for (int j = 0; j < 4; j++) c[j] = g_bitsT[(nbase + j) * BB + b];
    } else {                     // parity region: parity_m = XOR of DV info bits
#pragma unroll
        for (int j = 0; j < 4; j++) {
            int m = nbase + j - KK;
            int x = 0;
#pragma unroll
            for (int d = 0; d < DVx; d++)
                x ^= g_bitsT[__ldg(a_idx + m * DVx + d) * BB + b];
            c[j] = x;
        }
    }
    int sym = (c[0] << 3) | (c[1] << 2) | (c[2] << 1) | c[3];

    float yre = cr[sym] + sigma * nre[b * NSYMs + s];
    float yim = ci[sym] + sigma * nim[b * NSYMs + s];

    float lg[16];
#pragma unroll
    for (int i = 0; i < 16; i++) {
        float dr = yre - cr[i], di = yim - ci[i];
        lg[i] = (dr * dr + di * di) * inv;
    }

#pragma unroll
    for (int j = 0; j < 4; j++) {
        float m0 = -1e30f, m1 = -1e30f;
#pragma unroll
        for (int i = 0; i < 16; i++) {
            if ((i >> (3 - j)) & 1) m1 = fmaxf(m1, lg[i]);
            else                    m0 = fmaxf(m0, lg[i]);
        }
        float s0 = 0.f, s1 = 0.f;
#pragma unroll
        for (int i = 0; i < 16; i++) {
            if ((i >> (3 - j)) & 1) s1 += expf(lg[i] - m1);
            else                    s0 += expf(lg[i] - m0);
        }
        float llrv = (m0 + logf(s0)) - (m1 + logf(s1));
        int n = nbase + j;
        g_llr[n * BB + b] = llrv;
        g_L[n * BB + b] = llrv;   // initial posterior (c2v = 0)
    }
}

// ---------------- BP check-node update ----------------
// v2c_j = L[vn_j] - c2v_j ;  t_j = tanh(clip(|v2c|)/2)
// ex_j = min(prod_{i!=j} t_i, exp(-1e-7)) ;  c2v_j = sign * log((1+ex)/(1-ex))
__global__ void k_check(const int* __restrict__ vn) {
    int b = blockIdx.x * blockDim.x + threadIdx.x;
    int m = blockIdx.y;
    int base = m * 6;

    float t[6];
    int sg[6];
    int ns = 0;
#pragma unroll
    for (int j = 0; j < 6; j++) {
        int v = __ldg(vn + base + j);
        float cc = g_c2v[(base + j) * BB + b];
        float x = g_L[v * BB + b] - cc;
        int s = (x < 0.0f) ? 1 : 0;
        float a = fabsf(x);
        a = fminf(fmaxf(a, 1e-6f), 20.0f);
        float em = expm1f(-a);            // accurate for tiny a (no cancellation)
        t[j] = -em / (em + 2.0f);         // tanh(a/2)
        sg[j] = s;
        ns += s;
    }
    // product of all-but-one via prefix/suffix products (no divisions)
    float r[6];
    float acc = 1.0f;
#pragma unroll
    for (int j = 0; j < 6; j++) { r[j] = acc; acc *= t[j]; }
    acc = 1.0f;
#pragma unroll
    for (int j = 5; j >= 0; j--) { r[j] *= acc; acc *= t[j]; }

#pragma unroll
    for (int j = 0; j < 6; j++) {
        float ex = fminf(r[j], 0.99999988f);      // = expf(-1e-7f)
        float mag = logf((1.0f + ex) / (1.0f - ex));  // = 2*atanh(ex)
        float val = ((ns - sg[j]) & 1) ? -mag : mag;
        g_c2v[(base + j) * BB + b] = val;
    }
}

// ---------------- BP variable-node update (deterministic CSR gather) ----------------
__global__ void k_var() {
    int b = blockIdx.x * blockDim.x + threadIdx.x;
    int v = blockIdx.y;
    float s = g_llr[v * BB + b];
    int o0 = g_off[v], o1 = g_off[v + 1];
    for (int i = o0; i < o1; i++)
        s += g_c2v[g_var_edges[i] * BB + b];
    g_L[v * BB + b] = s;
}

// ---------------- output ----------------
__global__ void k_out(const int* __restrict__ bits, float* __restrict__ out) {
    int t = blockIdx.x * blockDim.x + threadIdx.x;
    if (t < BB * KK) {
        int b = t / KK, k = t - b * KK;
        out[t] = (float)bits[t];
        out[BB * KK + t] = (g_L[k * BB + b] < 0.0f) ? 1.0f : 0.0f;
    }
}

extern "C" void kernel_launch(void* const* d_in, const int* in_sizes, int n_in,
                              void* d_out, int out_size) {
    const int*   bits    = (const int*)d_in[0];
    const int*   a_idx   = (const int*)d_in[1];
    // d_in[2] = edge_cn (implied by structure: edges 6m..6m+5 belong to check m)
    const int*   edge_vn = (const int*)d_in[3];
    const float* pre     = (const float*)d_in[4];
    const float* pim     = (const float*)d_in[5];
    const float* nre     = (const float*)d_in[6];
    const float* nim     = (const float*)d_in[7];
    const float* ebno    = (const float*)d_in[8];
    float* out = (float*)d_out;

    k_transpose<<<(BB * KK + 255) / 256, 256>>>(bits);
    k_zero_cnt<<<(NN + 255) / 256, 256>>>();
    k_count<<<(EE + 255) / 256, 256>>>(edge_vn);
    k_scan<<<1, 1024>>>();
    k_fill<<<(EE + 255) / 256, 256>>>(edge_vn);
    k_zero_c2v<<<(EE * BB / 4 + 255) / 256, 256>>>();

    k_demap<<<dim3(BB / 256, NSYMs), 256>>>(a_idx, pre, pim, nre, nim, ebno);

    for (int it = 0; it < NITERs; it++) {
        k_check<<<dim3(BB / 256, MM), 256>>>(edge_vn);
        k_var<<<dim3(BB / 256, NN), 256>>>();
    }

    k_out<<<(BB * KK + 255) / 256, 256>>>(bits, out);
}

// round 7
// speedup vs baseline: 1.6881x; 1.6881x over previous
#include <cuda_runtime.h>

#define KK    1056
#define NN    2112
#define MM    1056
#define DVx   5
#define E5    (MM * DVx)     // 5280 info-bit edges (parity edges eliminated)
#define NSYMs 528
#define BB    1024
#define B4    (BB / 4)       // 256 float4 lanes over batch
#define NITERs 20

// ---- static device scratch ----
__device__ float g_llr[KK * BB];            // intrinsic LLRs for info bits, [k][b]
__device__ float g_L[KK * BB];              // posterior for info bits, [k][b]
__device__ float g_c2v[E5 * BB];            // check->variable msgs (info edges), [e][b]
__device__ float g_pt[MM * BB];             // signed tanh(|llr_parity|/2), [m][b]
__device__ unsigned char g_bitsT[KK * BB];  // transposed info bits, [k][b]
__device__ float g_nreT[NSYMs * BB];        // transposed noise, [s][b]
__device__ float g_nimT[NSYMs * BB];
__device__ int g_cnt[KK];
__device__ int g_off[KK + 1];
__device__ int g_var_edges[E5];

// ---------------- math helpers (constants identical to passing kernel) ----------------
__device__ __forceinline__ float tanh_half_signed(float x) {
    float s = (x < 0.0f) ? -1.0f : 1.0f;
    float a = fminf(fmaxf(fabsf(x), 1e-6f), 20.0f);
    float em = expm1f(-a);                 // accurate near 0
    return s * (-em / (em + 2.0f));        // signed tanh(a/2)
}
__device__ __forceinline__ float atanh2_clamped(float r) {
    float ex = fminf(fmaxf(r, -0.99999988f), 0.99999988f);  // |ex| <= exp(-1e-7)
    return logf((1.0f + ex) / (1.0f - ex));                 // = 2*atanh(ex), odd
}
__device__ __forceinline__ float lse2(float a, float b) {
    float m = fmaxf(a, b);
    return m + log1pf(expf(-fabsf(a - b)));
}

// ---------------- tiled transposes ----------------
__global__ void k_tr_bits(const int* __restrict__ bits) {
    __shared__ int tile[32][33];
    int k0 = blockIdx.x * 32, b0 = blockIdx.y * 32;
    for (int r = threadIdx.y; r < 32; r += 8)
        tile[r][threadIdx.x] = bits[(b0 + r) * KK + (k0 + threadIdx.x)];
    __syncthreads();
    for (int r = threadIdx.y; r < 32; r += 8)
        g_bitsT[(k0 + r) * BB + (b0 + threadIdx.x)] = (unsigned char)tile[threadIdx.x][r];
}

__global__ void k_tr_noise(const float* __restrict__ nre, const float* __restrict__ nim) {
    __shared__ float t0[32][33], t1[32][33];
    int s0 = blockIdx.x * 32, b0 = blockIdx.y * 32;
    for (int r = threadIdx.y; r < 32; r += 8) {
        int s = s0 + threadIdx.x;
        if (s < NSYMs) {
            t0[r][threadIdx.x] = nre[(b0 + r) * NSYMs + s];
            t1[r][threadIdx.x] = nim[(b0 + r) * NSYMs + s];
        }
    }
    __syncthreads();
    for (int r = threadIdx.y; r < 32; r += 8) {
        int s = s0 + r;
        if (s < NSYMs) {
            g_nreT[s * BB + (b0 + threadIdx.x)] = t0[threadIdx.x][r];
            g_nimT[s * BB + (b0 + threadIdx.x)] = t1[threadIdx.x][r];
        }
    }
}

// ---------------- CSR build over info edges (deterministic: sorted edge ids) ----------------
__global__ void k_zero_cnt() {
    int t = blockIdx.x * blockDim.x + threadIdx.x;
    if (t < KK) g_cnt[t] = 0;
}
__global__ void k_count(const int* __restrict__ a_idx) {
    int e = blockIdx.x * blockDim.x + threadIdx.x;
    if (e < E5) atomicAdd(&g_cnt[a_idx[e]], 1);
}
__global__ void k_scan() {  // 1024 threads, 2 entries each (2048 >= KK+1)
    __shared__ int sh[1024];
    int tid = threadIdx.x, i0 = tid * 2;
    int c0 = (i0 < KK) ? g_cnt[i0] : 0;
    int c1 = (i0 + 1 < KK) ? g_cnt[i0 + 1] : 0;
    int sum = c0 + c1;
    sh[tid] = sum;
    __syncthreads();
    for (int off = 1; off < 1024; off <<= 1) {
        int v = (tid >= off) ? sh[tid - off] : 0;
        __syncthreads();
        sh[tid] += v;
        __syncthreads();
    }
    int base = sh[tid] - sum;
    if (i0 <= KK) g_off[i0] = base;
    if (i0 + 1 <= KK) g_off[i0 + 1] = base + c0;
}
__global__ void k_fill(const int* __restrict__ a_idx) {
    int e = blockIdx.x * blockDim.x + threadIdx.x;
    if (e < E5) {
        int v = a_idx[e];
        int p = atomicAdd(&g_cnt[v], 1);     // nondeterministic order...
        g_var_edges[g_off[v] + p] = e;
    }
}
__global__ void k_sortE() {                  // ...made deterministic by sorting
    int v = blockIdx.x * blockDim.x + threadIdx.x;
    if (v < KK) {
        int o0 = g_off[v], o1 = g_off[v + 1];
        for (int i = o0 + 1; i < o1; i++) {
            int x = g_var_edges[i], j = i - 1;
            while (j >= o0 && g_var_edges[j] > x) { g_var_edges[j + 1] = g_var_edges[j]; j--; }
            g_var_edges[j + 1] = x;
        }
    }
}

// ---------------- encode + map + AWGN + separable APP demap ----------------
// Gray 16-QAM factors: real PAM from bits (b0,b2), imag from (b1,b3).
// LLR(b0)=LSE(re0,re1)-LSE(re2,re3); LLR(b2)=LSE(re0,re2)-LSE(re1,re3); imag likewise.
__global__ void k_demap(const int* __restrict__ a_idx,
                        const float* __restrict__ pre, const float* __restrict__ pim,
                        const float* __restrict__ ebno) {
    int t = threadIdx.x;       // float4 lane over batch
    int s = blockIdx.x;
    int b0 = t * 4;

    float eb = __ldg(ebno);
    float no = 1.0f / (exp10f(eb * 0.1f) * 0.5f * 4.0f);   // coderate 0.5, 4 bps
    float sigma = sqrtf(no * 0.5f);
    float inv = -1.0f / no;

    // 4-PAM levels: pr4[b0*2+b2] = points_re[b0<<3 | b2<<1], pi4[b1*2+b3] = points_im[b1<<2 | b3]
    float pr4[4] = { __ldg(pre + 0), __ldg(pre + 2), __ldg(pre + 8), __ldg(pre + 10) };
    float pi4[4] = { __ldg(pim + 0), __ldg(pim + 1), __ldg(pim + 4), __ldg(pim + 5) };

    int nbase = 4 * s;
    unsigned int cb[4];   // 4 bytes = bits for 4 batch lanes
    if (nbase < KK) {
#pragma unroll
        for (int j = 0; j < 4; j++)
            cb[j] = *(const unsigned int*)&g_bitsT[(nbase + j) * BB + b0];
    } else {
#pragma unroll
        for (int j = 0; j < 4; j++) {
            int m = nbase + j - KK;
            unsigned int x = 0;
#pragma unroll
            for (int d = 0; d < DVx; d++)
                x ^= *(const unsigned int*)&g_bitsT[__ldg(a_idx + m * DVx + d) * BB + b0];
            cb[j] = x;
        }
    }

    float4 nr = *(const float4*)&g_nreT[s * BB + b0];
    float4 ni = *(const float4*)&g_nimT[s * BB + b0];
    float nrl[4] = { nr.x, nr.y, nr.z, nr.w };
    float nil[4] = { ni.x, ni.y, ni.z, ni.w };

    float out[4][4];
#pragma unroll
    for (int l = 0; l < 4; l++) {
        int c0 = (cb[0] >> (8 * l)) & 1, c1 = (cb[1] >> (8 * l)) & 1;
        int c2 = (cb[2] >> (8 * l)) & 1, c3 = (cb[3] >> (8 * l)) & 1;
        float yre = pr4[(c0 << 1) | c2] + sigma * nrl[l];
        float yim = pi4[(c1 << 1) | c3] + sigma * nil[l];
        float lgre[4], lgim[4];
#pragma unroll
        for (int p = 0; p < 4; p++) {
            float d = yre - pr4[p]; lgre[p] = d * d * inv;
            d = yim - pi4[p];       lgim[p] = d * d * inv;
        }
        out[0][l] = lse2(lgre[0], lgre[1]) - lse2(lgre[2], lgre[3]);
        out[2][l] = lse2(lgre[0], lgre[2]) - lse2(lgre[1], lgre[3]);
        out[1][l] = lse2(lgim[0], lgim[1]) - lse2(lgim[2], lgim[3]);
        out[3][l] = lse2(lgim[0], lgim[2]) - lse2(lgim[1], lgim[3]);
    }

    if (nbase < KK) {
#pragma unroll
        for (int j = 0; j < 4; j++) {
            float4 v = make_float4(out[j][0], out[j][1], out[j][2], out[j][3]);
            *(float4*)&g_llr[(nbase + j) * BB + b0] = v;
        }
    } else {
#pragma unroll
        for (int j = 0; j < 4; j++) {   // parity: v2c is constant => precompute signed tanh
            int m = nbase + j - KK;
            float4 v = make_float4(tanh_half_signed(out[j][0]), tanh_half_signed(out[j][1]),
                                   tanh_half_signed(out[j][2]), tanh_half_signed(out[j][3]));
            *(float4*)&g_pt[m * BB + b0] = v;
        }
    }
}

// ---------------- BP check-node update (5 info edges + constant parity tanh) ----------------
template <int FIRST>
__global__ void k_check(const int* __restrict__ a_idx) {
    int t = threadIdx.x;
    int m = blockIdx.x;
    int b0 = t * 4;
    int base = m * 5;
    const float* Ls = FIRST ? g_llr : g_L;

    float4 tt[6];
#pragma unroll
    for (int j = 0; j < 5; j++) {
        int v = __ldg(a_idx + base + j);
        float4 L = *(const float4*)&Ls[v * BB + b0];
        float4 c = FIRST ? make_float4(0.f, 0.f, 0.f, 0.f)
                         : *(const float4*)&g_c2v[(base + j) * BB + b0];
        tt[j].x = tanh_half_signed(L.x - c.x);
        tt[j].y = tanh_half_signed(L.y - c.y);
        tt[j].z = tanh_half_signed(L.z - c.z);
        tt[j].w = tanh_half_signed(L.w - c.w);
    }
    tt[5] = *(const float4*)&g_pt[m * BB + b0];   // signed parity tanh (constant)

    // all-but-one products via prefix/suffix (sign carried in the product)
    float4 r[5];
    float4 acc = make_float4(1.f, 1.f, 1.f, 1.f);
#pragma unroll
    for (int j = 0; j < 5; j++) {
        r[j] = acc;
        acc.x *= tt[j].x; acc.y *= tt[j].y; acc.z *= tt[j].z; acc.w *= tt[j].w;
    }
    acc = tt[5];
#pragma unroll
    for (int j = 4; j >= 0; j--) {
        r[j].x *= acc.x; r[j].y *= acc.y; r[j].z *= acc.z; r[j].w *= acc.w;
        acc.x *= tt[j].x; acc.y *= tt[j].y; acc.z *= tt[j].z; acc.w *= tt[j].w;
    }
#pragma unroll
    for (int j = 0; j < 5; j++) {
        float4 o;
        o.x = atanh2_clamped(r[j].x);
        o.y = atanh2_clamped(r[j].y);
        o.z = atanh2_clamped(r[j].z);
        o.w = atanh2_clamped(r[j].w);
        *(float4*)&g_c2v[(base + j) * BB + b0] = o;
    }
}

// ---------------- BP variable-node update (info bits only; deterministic sorted CSR) --------
__global__ void k_var() {
    int t = threadIdx.x;
    int v = blockIdx.x;
    int b0 = t * 4;
    float4 s = *(const float4*)&g_llr[v * BB + b0];
    int o0 = __ldg(&g_off[v]), o1 = __ldg(&g_off[v + 1]);
    for (int i = o0; i < o1; i++) {
        int e = __ldg(&g_var_edges[i]);
        float4 c = *(const float4*)&g_c2v[e * BB + b0];
        s.x += c.x; s.y += c.y; s.z += c.z; s.w += c.w;
    }
    *(float4*)&g_L[v * BB + b0] = s;
}

// ---------------- output (tiled transpose of L) ----------------
__global__ void k_out(const int* __restrict__ bits, float* __restrict__ out) {
    __shared__ float tile[32][33];
    int k0 = blockIdx.x * 32, b0 = blockIdx.y * 32;
    for (int r = threadIdx.y; r < 32; r += 8)
        tile[r][threadIdx.x] = g_L[(k0 + r) * BB + (b0 + threadIdx.x)];
    __syncthreads();
    for (int r = threadIdx.y; r < 32; r += 8) {
        int b = b0 + r, k = k0 + threadIdx.x;
        out[b * KK + k] = (float)bits[b * KK + k];
        out[BB * KK + b * KK + k] = (tile[threadIdx.x][r] < 0.0f) ? 1.0f : 0.0f;
    }
}

extern "C" void kernel_launch(void* const* d_in, const int* in_sizes, int n_in,
                              void* d_out, int out_size) {
    const int*   bits  = (const int*)d_in[0];
    const int*   a_idx = (const int*)d_in[1];
    const float* pre   = (const float*)d_in[4];
    const float* pim   = (const float*)d_in[5];
    const float* nre   = (const float*)d_in[6];
    const float* nim   = (const float*)d_in[7];
    const float* ebno  = (const float*)d_in[8];
    float* out = (float*)d_out;

    k_tr_bits<<<dim3(KK / 32, BB / 32), dim3(32, 8)>>>(bits);
    k_tr_noise<<<dim3((NSYMs + 31) / 32, BB / 32), dim3(32, 8)>>>(nre, nim);

    k_zero_cnt<<<(KK + 255) / 256, 256>>>();
    k_count<<<(E5 + 255) / 256, 256>>>(a_idx);
    k_scan<<<1, 1024>>>();
    k_zero_cnt<<<(KK + 255) / 256, 256>>>();
    k_fill<<<(E5 + 255) / 256, 256>>>(a_idx);
    k_sortE<<<(KK + 255) / 256, 256>>>();

    k_demap<<<NSYMs, B4>>>(a_idx, pre, pim, ebno);

    k_check<1><<<MM, B4>>>(a_idx);
    k_var<<<KK, B4>>>();
    for (int it = 1; it < NITERs; it++) {
        k_check<0><<<MM, B4>>>(a_idx);
        k_var<<<KK, B4>>>();
    }

    k_out<<<dim3(KK / 32, BB / 32), dim3(32, 8)>>>(bits, out);
}

// round 8
// speedup vs baseline: 2.8939x; 1.7143x over previous
#include <cuda_runtime.h>

#define KK    1056
#define NN    2112
#define MM    1056
#define DVx   5
#define E5    (MM * DVx)     // 5280 info-bit edges (parity edges eliminated)
#define NSYMs 528
#define BB    1024
#define B4    (BB / 4)       // 256 float4 lanes over batch
#define NITERs 20

// ---- static device scratch ----
__device__ float g_llr[KK * BB];            // intrinsic LLRs for info bits, [k][b]
__device__ float g_L[KK * BB];              // posterior for info bits, [k][b]
__device__ float g_c2v[E5 * BB];            // check->variable msgs (info edges), [e][b]
__device__ float g_pt[MM * BB];             // signed tanh(|llr_parity|/2), [m][b]
__device__ unsigned char g_bitsT[KK * BB];  // transposed info bits, [k][b]
__device__ float g_nreT[NSYMs * BB];        // transposed noise, [s][b]
__device__ float g_nimT[NSYMs * BB];
__device__ int g_off[KK + 1];
__device__ int g_var_edges[E5];

// ---------------- math helpers ----------------
// precise path (used once, in demap / parity tanh seed)
__device__ __forceinline__ float tanh_half_signed(float x) {
    float s = (x < 0.0f) ? -1.0f : 1.0f;
    float a = fminf(fmaxf(fabsf(x), 1e-6f), 20.0f);
    float em = expm1f(-a);
    return s * (-em / (em + 2.0f));
}
// fast MUFU path (BP inner loop): same clamps, same math, EX2/RCP/LG2 hardware ops
__device__ __forceinline__ float tanh_half_fast(float x) {
    float a = fminf(fmaxf(fabsf(x), 1e-6f), 20.0f);
    float ex = __expf(-a);
    float t = __fdividef(1.0f - ex, 1.0f + ex);   // tanh(a/2)
    return copysignf(t, x);
}
__device__ __forceinline__ float atanh2_fast(float r) {
    float ex = fminf(fabsf(r), 0.99999988f);      // = expf(-1e-7f) cap
    float u = __fdividef(1.0f + ex, 1.0f - ex);
    return copysignf(__logf(u), r);               // 2*atanh(ex), odd
}
__device__ __forceinline__ float lse2(float a, float b) {
    float m = fmaxf(a, b);
    return m + log1pf(expf(-fabsf(a - b)));
}

// ---------------- tiled transposes ----------------
__global__ void k_tr_bits(const int* __restrict__ bits) {
    __shared__ int tile[32][33];
    int k0 = blockIdx.x * 32, b0 = blockIdx.y * 32;
    for (int r = threadIdx.y; r < 32; r += 8)
        tile[r][threadIdx.x] = bits[(b0 + r) * KK + (k0 + threadIdx.x)];
    __syncthreads();
    for (int r = threadIdx.y; r < 32; r += 8)
        g_bitsT[(k0 + r) * BB + (b0 + threadIdx.x)] = (unsigned char)tile[threadIdx.x][r];
}

__global__ void k_tr_noise(const float* __restrict__ nre, const float* __restrict__ nim) {
    __shared__ float t0[32][33], t1[32][33];
    int s0 = blockIdx.x * 32, b0 = blockIdx.y * 32;
    for (int r = threadIdx.y; r < 32; r += 8) {
        int s = s0 + threadIdx.x;
        if (s < NSYMs) {
            t0[r][threadIdx.x] = nre[(b0 + r) * NSYMs + s];
            t1[r][threadIdx.x] = nim[(b0 + r) * NSYMs + s];
        }
    }
    __syncthreads();
    for (int r = threadIdx.y; r < 32; r += 8) {
        int s = s0 + r;
        if (s < NSYMs) {
            g_nreT[s * BB + (b0 + threadIdx.x)] = t0[threadIdx.x][r];
            g_nimT[s * BB + (b0 + threadIdx.x)] = t1[threadIdx.x][r];
        }
    }
}

// ---------------- fused CSR build (single block; deterministic via final sort) --------
__global__ void k_csr(const int* __restrict__ a_idx) {
    __shared__ int cnt[KK];
    __shared__ int sh[1024];
    int tid = threadIdx.x;
    for (int i = tid; i < KK; i += 1024) cnt[i] = 0;
    __syncthreads();
    for (int e = tid; e < E5; e += 1024) atomicAdd(&cnt[a_idx[e]], 1);
    __syncthreads();
    // exclusive scan: 2 entries per thread
    int i0 = tid * 2;
    int c0 = (i0 < KK) ? cnt[i0] : 0;
    int c1 = (i0 + 1 < KK) ? cnt[i0 + 1] : 0;
    int sum = c0 + c1;
    sh[tid] = sum;
    __syncthreads();
    for (int off = 1; off < 1024; off <<= 1) {
        int v = (tid >= off) ? sh[tid - off] : 0;
        __syncthreads();
        sh[tid] += v;
        __syncthreads();
    }
    int base = sh[tid] - sum;
    if (i0 <= KK) g_off[i0] = base;
    if (i0 + 1 <= KK) g_off[i0 + 1] = base + c0;
    for (int i = tid; i < KK; i += 1024) cnt[i] = 0;
    __syncthreads();   // also fences the g_off global writes block-wide
    for (int e = tid; e < E5; e += 1024) {
        int v = a_idx[e];
        int p = atomicAdd(&cnt[v], 1);            // nondeterministic order...
        g_var_edges[g_off[v] + p] = e;
    }
    __syncthreads();
    for (int v = tid; v < KK; v += 1024) {        // ...made deterministic by sorting
        int o0 = g_off[v], o1 = g_off[v + 1];
        for (int i = o0 + 1; i < o1; i++) {
            int x = g_var_edges[i], j = i - 1;
            while (j >= o0 && g_var_edges[j] > x) { g_var_edges[j + 1] = g_var_edges[j]; j--; }
            g_var_edges[j + 1] = x;
        }
    }
}

// ---------------- encode + map + AWGN + separable APP demap ----------------
__global__ void k_demap(const int* __restrict__ a_idx,
                        const float* __restrict__ pre, const float* __restrict__ pim,
                        const float* __restrict__ ebno) {
    int t = threadIdx.x;       // float4 lane over batch
    int s = blockIdx.x;
    int b0 = t * 4;

    float eb = __ldg(ebno);
    float no = 1.0f / (exp10f(eb * 0.1f) * 0.5f * 4.0f);   // coderate 0.5, 4 bps
    float sigma = sqrtf(no * 0.5f);
    float inv = -1.0f / no;

    float pr4[4] = { __ldg(pre + 0), __ldg(pre + 2), __ldg(pre + 8), __ldg(pre + 10) };
    float pi4[4] = { __ldg(pim + 0), __ldg(pim + 1), __ldg(pim + 4), __ldg(pim + 5) };

    int nbase = 4 * s;
    unsigned int cb[4];
    if (nbase < KK) {
#pragma unroll
        for (int j = 0; j < 4; j++)
            cb[j] = *(const unsigned int*)&g_bitsT[(nbase + j) * BB + b0];
    } else {
#pragma unroll
        for (int j = 0; j < 4; j++) {
            int m = nbase + j - KK;
            unsigned int x = 0;
#pragma unroll
            for (int d = 0; d < DVx; d++)
                x ^= *(const unsigned int*)&g_bitsT[__ldg(a_idx + m * DVx + d) * BB + b0];
            cb[j] = x;
        }
    }

    float4 nr = *(const float4*)&g_nreT[s * BB + b0];
    float4 ni = *(const float4*)&g_nimT[s * BB + b0];
    float nrl[4] = { nr.x, nr.y, nr.z, nr.w };
    float nil[4] = { ni.x, ni.y, ni.z, ni.w };

    float out[4][4];
#pragma unroll
    for (int l = 0; l < 4; l++) {
        int c0 = (cb[0] >> (8 * l)) & 1, c1 = (cb[1] >> (8 * l)) & 1;
        int c2 = (cb[2] >> (8 * l)) & 1, c3 = (cb[3] >> (8 * l)) & 1;
        float yre = pr4[(c0 << 1) | c2] + sigma * nrl[l];
        float yim = pi4[(c1 << 1) | c3] + sigma * nil[l];
        float lgre[4], lgim[4];
#pragma unroll
        for (int p = 0; p < 4; p++) {
            float d = yre - pr4[p]; lgre[p] = d * d * inv;
            d = yim - pi4[p];       lgim[p] = d * d * inv;
        }
        out[0][l] = lse2(lgre[0], lgre[1]) - lse2(lgre[2], lgre[3]);
        out[2][l] = lse2(lgre[0], lgre[2]) - lse2(lgre[1], lgre[3]);
        out[1][l] = lse2(lgim[0], lgim[1]) - lse2(lgim[2], lgim[3]);
        out[3][l] = lse2(lgim[0], lgim[2]) - lse2(lgim[1], lgim[3]);
    }

    if (nbase < KK) {
#pragma unroll
        for (int j = 0; j < 4; j++) {
            float4 v = make_float4(out[j][0], out[j][1], out[j][2], out[j][3]);
            *(float4*)&g_llr[(nbase + j) * BB + b0] = v;
        }
    } else {
#pragma unroll
        for (int j = 0; j < 4; j++) {   // parity deg-1: constant signed tanh, precise path
            int m = nbase + j - KK;
            float4 v = make_float4(tanh_half_signed(out[j][0]), tanh_half_signed(out[j][1]),
                                   tanh_half_signed(out[j][2]), tanh_half_signed(out[j][3]));
            *(float4*)&g_pt[m * BB + b0] = v;
        }
    }
}

// ---------------- BP check-node update (fast MUFU transcendentals) ----------------
template <int FIRST>
__global__ void __launch_bounds__(B4) k_check(const int* __restrict__ a_idx) {
    int t = threadIdx.x;
    int m = blockIdx.x;
    int b0 = t * 4;
    int base = m * 5;
    const float* Ls = FIRST ? g_llr : g_L;

    float4 tt[6];
#pragma unroll
    for (int j = 0; j < 5; j++) {
        int v = __ldg(a_idx + base + j);
        float4 L = *(const float4*)&Ls[v * BB + b0];
        float4 c = FIRST ? make_float4(0.f, 0.f, 0.f, 0.f)
                         : *(const float4*)&g_c2v[(base + j) * BB + b0];
        tt[j].x = tanh_half_fast(L.x - c.x);
        tt[j].y = tanh_half_fast(L.y - c.y);
        tt[j].z = tanh_half_fast(L.z - c.z);
        tt[j].w = tanh_half_fast(L.w - c.w);
    }
    tt[5] = *(const float4*)&g_pt[m * BB + b0];   // constant parity tanh (signed)

    // all-but-one products via prefix/suffix (sign carried in product)
    float4 r[5];
    float4 acc = make_float4(1.f, 1.f, 1.f, 1.f);
#pragma unroll
    for (int j = 0; j < 5; j++) {
        r[j] = acc;
        acc.x *= tt[j].x; acc.y *= tt[j].y; acc.z *= tt[j].z; acc.w *= tt[j].w;
    }
    acc = tt[5];
#pragma unroll
    for (int j = 4; j >= 0; j--) {
        r[j].x *= acc.x; r[j].y *= acc.y; r[j].z *= acc.z; r[j].w *= acc.w;
        acc.x *= tt[j].x; acc.y *= tt[j].y; acc.z *= tt[j].z; acc.w *= tt[j].w;
    }
#pragma unroll
    for (int j = 0; j < 5; j++) {
        float4 o;
        o.x = atanh2_fast(r[j].x);
        o.y = atanh2_fast(r[j].y);
        o.z = atanh2_fast(r[j].z);
        o.w = atanh2_fast(r[j].w);
        *(float4*)&g_c2v[(base + j) * BB + b0] = o;
    }
}

// ---------------- BP variable-node update (sorted CSR, deterministic) ----------------
__global__ void __launch_bounds__(B4) k_var() {
    int t = threadIdx.x;
    int v = blockIdx.x;
    int b0 = t * 4;
    float4 s = *(const float4*)&g_llr[v * BB + b0];
    int o0 = __ldg(&g_off[v]), o1 = __ldg(&g_off[v + 1]);
    for (int i = o0; i < o1; i++) {
        int e = __ldg(&g_var_edges[i]);
        float4 c = *(const float4*)&g_c2v[e * BB + b0];
        s.x += c.x; s.y += c.y; s.z += c.z; s.w += c.w;
    }
    *(float4*)&g_L[v * BB + b0] = s;
}

// ---------------- output (tiled transpose of L) ----------------
__global__ void k_out(const int* __restrict__ bits, float* __restrict__ out) {
    __shared__ float tile[32][33];
    int k0 = blockIdx.x * 32, b0 = blockIdx.y * 32;
    for (int r = threadIdx.y; r < 32; r += 8)
        tile[r][threadIdx.x] = g_L[(k0 + r) * BB + (b0 + threadIdx.x)];
    __syncthreads();
    for (int r = threadIdx.y; r < 32; r += 8) {
        int b = b0 + r, k = k0 + threadIdx.x;
        out[b * KK + k] = (float)bits[b * KK + k];
        out[BB * KK + b * KK + k] = (tile[threadIdx.x][r] < 0.0f) ? 1.0f : 0.0f;
    }
}

extern "C" void kernel_launch(void* const* d_in, const int* in_sizes, int n_in,
                              void* d_out, int out_size) {
    const int*   bits  = (const int*)d_in[0];
    const int*   a_idx = (const int*)d_in[1];
    const float* pre   = (const float*)d_in[4];
    const float* pim   = (const float*)d_in[5];
    const float* nre   = (const float*)d_in[6];
    const float* nim   = (const float*)d_in[7];
    const float* ebno  = (const float*)d_in[8];
    float* out = (float*)d_out;

    k_tr_bits<<<dim3(KK / 32, BB / 32), dim3(32, 8)>>>(bits);
    k_tr_noise<<<dim3((NSYMs + 31) / 32, BB / 32), dim3(32, 8)>>>(nre, nim);
    k_csr<<<1, 1024>>>(a_idx);

    k_demap<<<NSYMs, B4>>>(a_idx, pre, pim, ebno);

    k_check<1><<<MM, B4>>>(a_idx);
    k_var<<<KK, B4>>>();
    for (int it = 1; it < NITERs; it++) {
        k_check<0><<<MM, B4>>>(a_idx);
        k_var<<<KK, B4>>>();
    }

    k_out<<<dim3(KK / 32, BB / 32), dim3(32, 8)>>>(bits, out);
}